// round 15
// baseline (speedup 1.0000x reference)
#include <cuda_runtime.h>
#include <math.h>
#include <stdint.h>

#define BB   8
#define NN   2048
#define FIN  512
#define FOUT 256

__device__ float g_h[(size_t)BB * NN * FOUT];   // tf32-prerounded h
__device__ float g_f[BB * NN];
__device__ float g_g[BB * NN];
__device__ float g_w12[2 * FIN];                // w1 = W@a1, w2 = W@a2

__device__ __forceinline__ uint32_t to_tf32(float f) {
    uint32_t r; asm("cvt.rna.tf32.f32 %0, %1;" : "=r"(r) : "f"(f)); return r;
}
__device__ __forceinline__ void mma_tf32(float* d, const uint32_t* a, const uint32_t* b) {
    asm volatile(
        "mma.sync.aligned.m16n8k8.row.col.f32.tf32.tf32.f32 "
        "{%0,%1,%2,%3}, {%4,%5,%6,%7}, {%8,%9}, {%0,%1,%2,%3};"
        : "+f"(d[0]), "+f"(d[1]), "+f"(d[2]), "+f"(d[3])
        : "r"(a[0]), "r"(a[1]), "r"(a[2]), "r"(a[3]), "r"(b[0]), "r"(b[1]));
}
__device__ __forceinline__ uint32_t smem_u32(const void* p) {
    uint32_t a;
    asm("{ .reg .u64 t; cvta.to.shared.u64 t, %1; cvt.u32.u64 %0, t; }" : "=r"(a) : "l"(p));
    return a;
}
__device__ __forceinline__ void cp16(uint32_t dst, const void* src) {
    asm volatile("cp.async.cg.shared.global [%0], [%1], 16;" :: "r"(dst), "l"(src));
}
#define CP_COMMIT() asm volatile("cp.async.commit_group;" ::: "memory")
#define CP_WAIT0()  asm volatile("cp.async.wait_group 0;" ::: "memory")

// ===========================================================================
// Kernel 0: w1 = W @ a1, w2 = W @ a2 (fp32).
// ===========================================================================
__global__ __launch_bounds__(256, 1)
void wv_kernel(const float* __restrict__ W, const float* __restrict__ a)
{
    const int warp = threadIdx.x >> 5, lane = threadIdx.x & 31;
    const int k = blockIdx.x * 8 + warp;
    const float* wr = W + (size_t)k * FOUT;
    float s1 = 0.f, s2 = 0.f;
    #pragma unroll
    for (int q = 0; q < 2; q++) {
        float4 wv = *(const float4*)(wr + lane * 8 + q * 4);
        float4 a1 = *(const float4*)(a + lane * 8 + q * 4);
        float4 a2 = *(const float4*)(a + FOUT + lane * 8 + q * 4);
        s1 += wv.x * a1.x + wv.y * a1.y + wv.z * a1.z + wv.w * a1.w;
        s2 += wv.x * a2.x + wv.y * a2.y + wv.z * a2.z + wv.w * a2.w;
    }
    #pragma unroll
    for (int d = 16; d >= 1; d >>= 1) {
        s1 += __shfl_xor_sync(0xffffffffu, s1, d);
        s2 += __shfl_xor_sync(0xffffffffu, s2, d);
    }
    if (lane == 0) { g_w12[k] = s1; g_w12[FIN + k] = s2; }
}

// ===========================================================================
// Kernel 2: f = x @ w1, g = x @ w2 (fp32 FFMA, HBM-bound).
// ===========================================================================
__global__ __launch_bounds__(256, 1)
void fg_kernel(const float* __restrict__ x)
{
    const int warp = threadIdx.x >> 5, lane = threadIdx.x & 31;
    const int row = blockIdx.x * 8 + warp;
    const float* xr = x + (size_t)row * FIN;
    float f = 0.f, g = 0.f;
    #pragma unroll
    for (int q = 0; q < 4; q++) {
        float4 v  = *(const float4*)(xr + lane * 4 + q * 128);
        float4 w1 = *(const float4*)(g_w12 + lane * 4 + q * 128);
        float4 w2 = *(const float4*)(g_w12 + FIN + lane * 4 + q * 128);
        f += v.x * w1.x + v.y * w1.y + v.z * w1.z + v.w * w1.w;
        g += v.x * w2.x + v.y * w2.y + v.z * w2.z + v.w * w2.w;
    }
    #pragma unroll
    for (int d = 16; d >= 1; d >>= 1) {
        f += __shfl_xor_sync(0xffffffffu, f, d);
        g += __shfl_xor_sync(0xffffffffu, g, d);
    }
    if (lane == 0) { g_f[row] = f; g_g[row] = g; }
}

// ===========================================================================
// Kernel 1: h = x @ W, single tf32 MMA. (R13, proven)
// ===========================================================================
#define XS_OFF 0
#define XS_SZ  2560
#define WS_OFF 5120
#define WS_SZ  4224
#define GH_SMEM 54272

__global__ __launch_bounds__(512, 1)
void gemm_h_kernel(const float* __restrict__ x, const float* __restrict__ W)
{
    extern __shared__ float sm[];
    const uint32_t sb = smem_u32(sm);

    const int t    = threadIdx.x;
    const int m0   = blockIdx.x * 128;
    const int warp = t >> 5, lane = t & 31;
    const int g    = lane >> 2, tig = lane & 3;
    const int wi   = warp >> 2, wo = warp & 3;

    const int xrow = t >> 2, xseg = (t & 3) * 4;
    const int wrow = t >> 5, wseg = (t & 31) * 8;
    const float* xsrc = x + (size_t)(m0 + xrow) * FIN + xseg;
    const float* wsrc = W + (size_t)wrow * FOUT + wseg;

    auto issue = [&](int s) {
        uint32_t xd = sb + (XS_OFF + (s & 1) * XS_SZ + xrow * 20 + xseg) * 4;
        cp16(xd, xsrc + s * 16);
        uint32_t wd = sb + (WS_OFF + (s & 1) * WS_SZ + wrow * 264 + wseg) * 4;
        cp16(wd,      wsrc + (size_t)s * 16 * FOUT);
        cp16(wd + 16, wsrc + (size_t)s * 16 * FOUT + 4);
        CP_COMMIT();
    };

    float acc[2][8][4];
    #pragma unroll
    for (int ma = 0; ma < 2; ma++)
        #pragma unroll
        for (int na = 0; na < 8; na++)
            #pragma unroll
            for (int c = 0; c < 4; c++) acc[ma][na][c] = 0.f;

    issue(0);
    CP_WAIT0();
    __syncthreads();

    for (int s = 0; s < 32; s++) {
        if (s < 31) issue(s + 1);
        const float* xs = sm + XS_OFF + (s & 1) * XS_SZ;
        const float* ws = sm + WS_OFF + (s & 1) * WS_SZ;

        #pragma unroll
        for (int ks = 0; ks < 2; ks++) {
            uint32_t bhi[8][2];
            #pragma unroll
            for (int na = 0; na < 8; na++) {
                int o = wo * 64 + na * 8 + g;
                bhi[na][0] = to_tf32(ws[(ks * 8 + tig) * 264 + o]);
                bhi[na][1] = to_tf32(ws[(ks * 8 + tig + 4) * 264 + o]);
            }
            #pragma unroll
            for (int ma = 0; ma < 2; ma++) {
                int R = wi * 32 + ma * 16;
                uint32_t ahi[4];
                ahi[0] = to_tf32(xs[(R + g) * 20 + ks * 8 + tig]);
                ahi[1] = to_tf32(xs[(R + g + 8) * 20 + ks * 8 + tig]);
                ahi[2] = to_tf32(xs[(R + g) * 20 + ks * 8 + tig + 4]);
                ahi[3] = to_tf32(xs[(R + g + 8) * 20 + ks * 8 + tig + 4]);
                #pragma unroll
                for (int na = 0; na < 8; na++)
                    mma_tf32(acc[ma][na], ahi, bhi[na]);
            }
        }
        if (s < 31) CP_WAIT0();
        __syncthreads();
    }

    #pragma unroll
    for (int ma = 0; ma < 2; ma++) {
        int ra = wi * 32 + ma * 16 + g;
        int rb = ra + 8;
        #pragma unroll
        for (int na = 0; na < 8; na++) {
            int col = wo * 64 + na * 8 + tig * 2;
            float2 sA = make_float2(__uint_as_float(to_tf32(acc[ma][na][0])),
                                    __uint_as_float(to_tf32(acc[ma][na][1])));
            float2 sB = make_float2(__uint_as_float(to_tf32(acc[ma][na][2])),
                                    __uint_as_float(to_tf32(acc[ma][na][3])));
            *(float2*)(g_h + (size_t)(m0 + ra) * FOUT + col) = sA;
            *(float2*)(g_h + (size_t)(m0 + rb) * FOUT + col) = sB;
        }
    }
}

// ===========================================================================
// Kernel 3: attention (R11 structure) + per-warp ks-phase STAGGER:
// ks = (ksx + warp) & 3 — decorrelates the LDS/MMA convoy so crossbar and
// tensor phases overlap across warps instead of serializing.
// ===========================================================================
#define AT_DSUM 0
#define AT_GS   1024
#define AT_PS0  3072
#define AT_PS1  7680
#define AT_HS0  12288
#define AT_HS1  20736
#define AT_HS_SZ 8448
#define ATTN_SMEM (29184 * 4)

__global__ __launch_bounds__(1024, 1)
void attn_kernel(const int* __restrict__ adj, float* __restrict__ out)
{
    extern __shared__ float smf[];
    const uint32_t sb = smem_u32(smf);

    const int t    = threadIdx.x;
    const int b    = blockIdx.x >> 4;
    const int i0   = (blockIdx.x & 15) << 7;
    const int warp = t >> 5, lane = t & 31;
    const int g    = lane >> 2, tig = lane & 3;
    const int wiq  = warp >> 3, wo = warp & 7;

    const int irow = t >> 3;
    const int jq   = t & 7;
    const int hjr  = t >> 5;
    const int hoc  = (t & 31) * 8;

    for (int j = t; j < NN; j += 1024) smf[AT_GS + j] = g_g[b * NN + j];
    const float fv = g_f[b * NN + i0 + irow];
    const int*   adjrow = adj + ((size_t)b * NN + i0 + irow) * NN + jq * 4;
    const float* hb     = g_h + (size_t)b * NN * FOUT;

    float acc[2][4][4];
    #pragma unroll
    for (int ma = 0; ma < 2; ma++)
        #pragma unroll
        for (int na = 0; na < 4; na++)
            #pragma unroll
            for (int c = 0; c < 4; c++) acc[ma][na][c] = 0.f;
    float dloc = 0.f;

    auto cp_h = [&](int jt) {
        const float* src = hb + (size_t)(jt * 32 + hjr) * FOUT + hoc;
        uint32_t dst = sb + (AT_HS0 + (jt & 1) * AT_HS_SZ + hjr * 264 + hoc) * 4;
        cp16(dst,      src);
        cp16(dst + 16, src + 4);
        CP_COMMIT();
    };
    auto ld_adj = [&](int jtp, int4& av) {
        av = *(const int4*)(adjrow + jtp * 32);
    };
    auto store_p = [&](int jtp, const int4& v) {
        float* ps = smf + (jtp & 1 ? AT_PS1 : AT_PS0);
        const float* gsr = smf + AT_GS + jtp * 32 + jq * 4;
        float z0 = fv + gsr[0]; z0 = z0 >= 0.f ? z0 : 0.2f * z0;
        float z1 = fv + gsr[1]; z1 = z1 >= 0.f ? z1 : 0.2f * z1;
        float z2 = fv + gsr[2]; z2 = z2 >= 0.f ? z2 : 0.2f * z2;
        float z3 = fv + gsr[3]; z3 = z3 >= 0.f ? z3 : 0.2f * z3;
        float p0 = (v.x > 0) ? __expf(z0) : 0.f;
        float p1 = (v.y > 0) ? __expf(z1) : 0.f;
        float p2 = (v.z > 0) ? __expf(z2) : 0.f;
        float p3 = (v.w > 0) ? __expf(z3) : 0.f;
        dloc += p0 + p1 + p2 + p3;
        float4 st = make_float4(__uint_as_float(to_tf32(p0)),
                                __uint_as_float(to_tf32(p1)),
                                __uint_as_float(to_tf32(p2)),
                                __uint_as_float(to_tf32(p3)));
        *(float4*)(ps + irow * 36 + jq * 4) = st;
    };
    auto do_mma = [&](int jt) {
        const uint32_t* psu = (const uint32_t*)(smf + (jt & 1 ? AT_PS1 : AT_PS0));
        const uint32_t* hsu = (const uint32_t*)(smf + (jt & 1 ? AT_HS1 : AT_HS0));
        #pragma unroll
        for (int ksx = 0; ksx < 4; ksx++) {
            const int ks = (ksx + warp) & 3;   // per-warp phase stagger
            uint32_t afr[2][4];
            #pragma unroll
            for (int ma = 0; ma < 2; ma++) {
                int base = (wiq * 32 + ma * 16 + g) * 36 + ks * 8 + tig;
                afr[ma][0] = psu[base];
                afr[ma][1] = psu[base + 8 * 36];
                afr[ma][2] = psu[base + 4];
                afr[ma][3] = psu[base + 8 * 36 + 4];
            }
            uint32_t bfr[4][2];
            #pragma unroll
            for (int na = 0; na < 4; na++) {
                int o = wo * 32 + na * 8 + g;
                bfr[na][0] = hsu[(ks * 8 + tig) * 264 + o];
                bfr[na][1] = hsu[(ks * 8 + tig + 4) * 264 + o];
            }
            #pragma unroll
            for (int ma = 0; ma < 2; ma++)
                #pragma unroll
                for (int na = 0; na < 4; na++)
                    mma_tf32(acc[ma][na], afr[ma], bfr[na]);
        }
    };

    int4 A0, A1;
    cp_h(0);
    ld_adj(0, A0);
    ld_adj(1, A1);
    CP_WAIT0();
    __syncthreads();
    store_p(0, A0);
    ld_adj(2, A0);
    __syncthreads();

    for (int jt = 0; jt < 64; jt += 2) {
        {
            if (jt < 63) cp_h(jt + 1);
            do_mma(jt);
            if (jt < 63) store_p(jt + 1, A1);
            if (jt + 3 < 64) ld_adj(jt + 3, A1);
            if (jt < 63) CP_WAIT0();
            __syncthreads();
        }
        {
            int jo = jt + 1;
            if (jo < 63) cp_h(jo + 1);
            do_mma(jo);
            if (jo < 63) store_p(jo + 1, A0);
            if (jo + 3 < 64) ld_adj(jo + 3, A0);
            if (jo < 63) CP_WAIT0();
            __syncthreads();
        }
    }

    smf[AT_DSUM + jq * 128 + irow] = dloc;
    __syncthreads();

    #pragma unroll
    for (int ma = 0; ma < 2; ma++) {
        int ra = wiq * 32 + ma * 16 + g;
        int rb = ra + 8;
        float da = 0.f, db = 0.f;
        #pragma unroll
        for (int s = 0; s < 8; s++) {
            da += smf[AT_DSUM + s * 128 + ra];
            db += smf[AT_DSUM + s * 128 + rb];
        }
        float inva = (da > 0.f) ? 1.f / da : 0.f;
        float invb = (db > 0.f) ? 1.f / db : 0.f;
        float* outa = out + ((size_t)b * NN + i0 + ra) * FOUT;
        float* outb = out + ((size_t)b * NN + i0 + rb) * FOUT;
        #pragma unroll
        for (int na = 0; na < 4; na++) {
            int col = wo * 32 + na * 8 + tig * 2;
            float v0 = acc[ma][na][0] * inva;
            float v1 = acc[ma][na][1] * inva;
            float v2 = acc[ma][na][2] * invb;
            float v3 = acc[ma][na][3] * invb;
            v0 = v0 > 0.f ? v0 : expm1f(v0);
            v1 = v1 > 0.f ? v1 : expm1f(v1);
            v2 = v2 > 0.f ? v2 : expm1f(v2);
            v3 = v3 > 0.f ? v3 : expm1f(v3);
            *(float2*)(outa + col) = make_float2(v0, v1);
            *(float2*)(outb + col) = make_float2(v2, v3);
        }
    }
}

// ---------------------------------------------------------------------------
extern "C" void kernel_launch(void* const* d_in, const int* in_sizes, int n_in,
                              void* d_out, int out_size)
{
    const float* x   = (const float*)d_in[0];
    const int*   adj = (const int*)d_in[1];
    const float* W   = (const float*)d_in[2];
    const float* a   = (const float*)d_in[3];
    float*       out = (float*)d_out;

    cudaFuncSetAttribute(gemm_h_kernel, cudaFuncAttributeMaxDynamicSharedMemorySize, GH_SMEM);
    cudaFuncSetAttribute(attn_kernel,   cudaFuncAttributeMaxDynamicSharedMemorySize, ATTN_SMEM);

    wv_kernel<<<64, 256>>>(W, a);
    gemm_h_kernel<<<128, 512, GH_SMEM>>>(x, W);
    fg_kernel<<<2048, 256>>>(x);
    attn_kernel<<<128, 1024, ATTN_SMEM>>>(adj, out);
}

// round 16
// speedup vs baseline: 1.3160x; 1.3160x over previous
#include <cuda_runtime.h>
#include <cuda_fp16.h>
#include <math.h>
#include <stdint.h>

#define BB   8
#define NN   2048
#define FIN  512
#define FOUT 256

__device__ __half g_hT[(size_t)BB * FOUT * NN];  // h transposed, fp16: [b][o][n]
__device__ float  g_f[BB * NN];
__device__ float  g_g[BB * NN];
__device__ float  g_w12[2 * FIN];

__device__ __forceinline__ uint32_t to_tf32(float f) {
    uint32_t r; asm("cvt.rna.tf32.f32 %0, %1;" : "=r"(r) : "f"(f)); return r;
}
__device__ __forceinline__ void mma_tf32(float* d, const uint32_t* a, const uint32_t* b) {
    asm volatile(
        "mma.sync.aligned.m16n8k8.row.col.f32.tf32.tf32.f32 "
        "{%0,%1,%2,%3}, {%4,%5,%6,%7}, {%8,%9}, {%0,%1,%2,%3};"
        : "+f"(d[0]), "+f"(d[1]), "+f"(d[2]), "+f"(d[3])
        : "r"(a[0]), "r"(a[1]), "r"(a[2]), "r"(a[3]), "r"(b[0]), "r"(b[1]));
}
__device__ __forceinline__ void mma_f16(float* d, const uint32_t* a, const uint32_t* b) {
    asm volatile(
        "mma.sync.aligned.m16n8k16.row.col.f32.f16.f16.f32 "
        "{%0,%1,%2,%3}, {%4,%5,%6,%7}, {%8,%9}, {%0,%1,%2,%3};"
        : "+f"(d[0]), "+f"(d[1]), "+f"(d[2]), "+f"(d[3])
        : "r"(a[0]), "r"(a[1]), "r"(a[2]), "r"(a[3]), "r"(b[0]), "r"(b[1]));
}
__device__ __forceinline__ uint32_t smem_u32(const void* p) {
    uint32_t a;
    asm("{ .reg .u64 t; cvta.to.shared.u64 t, %1; cvt.u32.u64 %0, t; }" : "=r"(a) : "l"(p));
    return a;
}
__device__ __forceinline__ void cp16(uint32_t dst, const void* src) {
    asm volatile("cp.async.cg.shared.global [%0], [%1], 16;" :: "r"(dst), "l"(src));
}
#define CP_COMMIT() asm volatile("cp.async.commit_group;" ::: "memory")
#define CP_WAIT0()  asm volatile("cp.async.wait_group 0;" ::: "memory")

// ===========================================================================
// Kernel 0: w1 = W @ a1, w2 = W @ a2 (fp32).
// ===========================================================================
__global__ __launch_bounds__(256, 1)
void wv_kernel(const float* __restrict__ W, const float* __restrict__ a)
{
    const int warp = threadIdx.x >> 5, lane = threadIdx.x & 31;
    const int k = blockIdx.x * 8 + warp;
    const float* wr = W + (size_t)k * FOUT;
    float s1 = 0.f, s2 = 0.f;
    #pragma unroll
    for (int q = 0; q < 2; q++) {
        float4 wv = *(const float4*)(wr + lane * 8 + q * 4);
        float4 a1 = *(const float4*)(a + lane * 8 + q * 4);
        float4 a2 = *(const float4*)(a + FOUT + lane * 8 + q * 4);
        s1 += wv.x * a1.x + wv.y * a1.y + wv.z * a1.z + wv.w * a1.w;
        s2 += wv.x * a2.x + wv.y * a2.y + wv.z * a2.z + wv.w * a2.w;
    }
    #pragma unroll
    for (int d = 16; d >= 1; d >>= 1) {
        s1 += __shfl_xor_sync(0xffffffffu, s1, d);
        s2 += __shfl_xor_sync(0xffffffffu, s2, d);
    }
    if (lane == 0) { g_w12[k] = s1; g_w12[FIN + k] = s2; }
}

// ===========================================================================
// Kernel 2: f = x @ w1, g = x @ w2 (fp32 FFMA).
// ===========================================================================
__global__ __launch_bounds__(256, 1)
void fg_kernel(const float* __restrict__ x)
{
    const int warp = threadIdx.x >> 5, lane = threadIdx.x & 31;
    const int row = blockIdx.x * 8 + warp;
    const float* xr = x + (size_t)row * FIN;
    float f = 0.f, g = 0.f;
    #pragma unroll
    for (int q = 0; q < 4; q++) {
        float4 v  = *(const float4*)(xr + lane * 4 + q * 128);
        float4 w1 = *(const float4*)(g_w12 + lane * 4 + q * 128);
        float4 w2 = *(const float4*)(g_w12 + FIN + lane * 4 + q * 128);
        f += v.x * w1.x + v.y * w1.y + v.z * w1.z + v.w * w1.w;
        g += v.x * w2.x + v.y * w2.y + v.z * w2.z + v.w * w2.w;
    }
    #pragma unroll
    for (int d = 16; d >= 1; d >>= 1) {
        f += __shfl_xor_sync(0xffffffffu, f, d);
        g += __shfl_xor_sync(0xffffffffu, g, d);
    }
    if (lane == 0) { g_f[row] = f; g_g[row] = g; }
}

// ===========================================================================
// Kernel 1: h = x @ W (single tf32 MMA), epilogue: smem transpose ->
// g_hT fp16 [b][o][n] with coalesced STG. 128 blocks x 512 threads.
// loop smem 54272 B; staging 256 x 136 halves = 69632 B -> GH_SMEM 69632.
// ===========================================================================
#define XS_OFF 0
#define XS_SZ  2560
#define WS_OFF 5120
#define WS_SZ  4224
#define GH_SMEM 69632
#define HSTP 136   // staging pitch in halves

__global__ __launch_bounds__(512, 1)
void gemm_h_kernel(const float* __restrict__ x, const float* __restrict__ W)
{
    extern __shared__ float sm[];
    const uint32_t sb = smem_u32(sm);

    const int t    = threadIdx.x;
    const int m0   = blockIdx.x * 128;
    const int warp = t >> 5, lane = t & 31;
    const int g    = lane >> 2, tig = lane & 3;
    const int wi   = warp >> 2, wo = warp & 3;

    const int xrow = t >> 2, xseg = (t & 3) * 4;
    const int wrow = t >> 5, wseg = (t & 31) * 8;
    const float* xsrc = x + (size_t)(m0 + xrow) * FIN + xseg;
    const float* wsrc = W + (size_t)wrow * FOUT + wseg;

    auto issue = [&](int s) {
        uint32_t xd = sb + (XS_OFF + (s & 1) * XS_SZ + xrow * 20 + xseg) * 4;
        cp16(xd, xsrc + s * 16);
        uint32_t wd = sb + (WS_OFF + (s & 1) * WS_SZ + wrow * 264 + wseg) * 4;
        cp16(wd,      wsrc + (size_t)s * 16 * FOUT);
        cp16(wd + 16, wsrc + (size_t)s * 16 * FOUT + 4);
        CP_COMMIT();
    };

    float acc[2][8][4];
    #pragma unroll
    for (int ma = 0; ma < 2; ma++)
        #pragma unroll
        for (int na = 0; na < 8; na++)
            #pragma unroll
            for (int c = 0; c < 4; c++) acc[ma][na][c] = 0.f;

    issue(0);
    CP_WAIT0();
    __syncthreads();

    for (int s = 0; s < 32; s++) {
        if (s < 31) issue(s + 1);
        const float* xs = sm + XS_OFF + (s & 1) * XS_SZ;
        const float* ws = sm + WS_OFF + (s & 1) * WS_SZ;

        #pragma unroll
        for (int ks = 0; ks < 2; ks++) {
            uint32_t bhi[8][2];
            #pragma unroll
            for (int na = 0; na < 8; na++) {
                int o = wo * 64 + na * 8 + g;
                bhi[na][0] = to_tf32(ws[(ks * 8 + tig) * 264 + o]);
                bhi[na][1] = to_tf32(ws[(ks * 8 + tig + 4) * 264 + o]);
            }
            #pragma unroll
            for (int ma = 0; ma < 2; ma++) {
                int R = wi * 32 + ma * 16;
                uint32_t ahi[4];
                ahi[0] = to_tf32(xs[(R + g) * 20 + ks * 8 + tig]);
                ahi[1] = to_tf32(xs[(R + g + 8) * 20 + ks * 8 + tig]);
                ahi[2] = to_tf32(xs[(R + g) * 20 + ks * 8 + tig + 4]);
                ahi[3] = to_tf32(xs[(R + g + 8) * 20 + ks * 8 + tig + 4]);
                #pragma unroll
                for (int na = 0; na < 8; na++)
                    mma_tf32(acc[ma][na], ahi, bhi[na]);
            }
        }
        if (s < 31) CP_WAIT0();
        __syncthreads();
    }

    // ---- stage transpose to fp16 ----
    __half* hst = (__half*)sm;
    #pragma unroll
    for (int ma = 0; ma < 2; ma++) {
        int ra = wi * 32 + ma * 16 + g;
        int rb = ra + 8;
        #pragma unroll
        for (int na = 0; na < 8; na++) {
            int col = wo * 64 + na * 8 + tig * 2;
            hst[(col    ) * HSTP + ra] = __float2half_rn(acc[ma][na][0]);
            hst[(col + 1) * HSTP + ra] = __float2half_rn(acc[ma][na][1]);
            hst[(col    ) * HSTP + rb] = __float2half_rn(acc[ma][na][2]);
            hst[(col + 1) * HSTP + rb] = __float2half_rn(acc[ma][na][3]);
        }
    }
    __syncthreads();

    // ---- coalesced STG: thread t writes 64 halves of row o = t>>1 ----
    {
        const int bidx = m0 >> 11;
        const int n0   = m0 & 2047;
        const int o    = t >> 1;
        const int seg  = (t & 1) * 64;
        __half* dst = g_hT + ((size_t)(bidx * 256 + o)) * NN + n0 + seg;
        const __half* srcr = hst + o * HSTP + seg;
        #pragma unroll
        for (int q = 0; q < 8; q++)
            *(uint4*)(dst + q * 8) = *(const uint4*)(srcr + q * 8);
    }
}

// ===========================================================================
// Kernel 3: attention, fp16 m16n8k16 MMA with softmax shift.
// 1024 threads, warp grid 4(i) x 8(o), j-tile 32, double-buffered.
// smem floats: dsum[1024]@0 | gs[2048]@1024 | red[32]@3072 |
//   ps(half,pitch40) 2x2560f @3104,5664 | hs(half,pitch40) 2x5120f @8224,13344
// total 18464 floats = 73856 B
// ===========================================================================
#define AT_DSUM 0
#define AT_GS   1024
#define AT_RED  3072
#define AT_PS0F 3104
#define AT_PS1F 5664
#define AT_HS0F 8224
#define AT_HS1F 13344
#define ATTN_SMEM (18464 * 4)

__global__ __launch_bounds__(1024, 1)
void attn_kernel(const int* __restrict__ adj, float* __restrict__ out)
{
    extern __shared__ float smf[];
    const uint32_t sb = smem_u32(smf);

    const int t    = threadIdx.x;
    const int b    = blockIdx.x >> 4;
    const int i0   = (blockIdx.x & 15) << 7;
    const int warp = t >> 5, lane = t & 31;
    const int g    = lane >> 2, tig = lane & 3;
    const int wiq  = warp >> 3, wo = warp & 7;

    // producer roles
    const int irow = t >> 3;        // 0..127 (p row)
    const int jq   = t & 7;         // j-eighth of 32 (4 each)
    const int ho   = t >> 2;        // 0..255 (hT row for cp)
    const int hseg = (t & 3) * 8;   // 8 halves = 16 B

    float acc[2][4][4];
    #pragma unroll
    for (int ma = 0; ma < 2; ma++)
        #pragma unroll
        for (int na = 0; na < 4; na++)
            #pragma unroll
            for (int c = 0; c < 4; c++) acc[ma][na][c] = 0.f;
    float dloc = 0.f;

    auto cp_h = [&](int jt) {
        const __half* src = g_hT + ((size_t)(b * 256 + ho)) * NN + jt * 32 + hseg;
        uint32_t dst = sb + ((jt & 1) ? AT_HS1F : AT_HS0F) * 4 + ho * 80 + hseg * 2;
        cp16(dst, src);
        CP_COMMIT();
    };
    auto ld_adj_at = [&](int jtp, int4& av, const int* adjrow) {
        av = *(const int4*)(adjrow + jtp * 32);
    };

    // ---- prologue: issue h(0), load gs, compute gmax ----
    cp_h(0);
    const int* adjrow = adj + ((size_t)b * NN + i0 + irow) * NN + jq * 4;
    int4 A0, A1;
    A0 = *(const int4*)(adjrow);
    A1 = *(const int4*)(adjrow + 32);
    float gm = -1e30f;
    for (int j = t; j < NN; j += 1024) {
        float v = g_g[b * NN + j];
        smf[AT_GS + j] = v;
        gm = fmaxf(gm, v);
    }
    const float fv = g_f[b * NN + i0 + irow];
    #pragma unroll
    for (int d = 16; d >= 1; d >>= 1) gm = fmaxf(gm, __shfl_xor_sync(0xffffffffu, gm, d));
    if (lane == 0) smf[AT_RED + warp] = gm;
    __syncthreads();
    if (warp == 0) {
        float v = smf[AT_RED + lane];
        #pragma unroll
        for (int d = 16; d >= 1; d >>= 1) v = fmaxf(v, __shfl_xor_sync(0xffffffffu, v, d));
        if (lane == 0) smf[AT_RED] = v;
    }
    __syncthreads();
    const float gmaxv = smf[AT_RED];
    float Mi = fv + gmaxv;
    Mi = (Mi >= 0.f) ? Mi : 0.2f * Mi;   // = max_j lrelu(fv + g_j)

    auto store_p = [&](int jtp, const int4& v) {
        __half* ps = (__half*)(smf + ((jtp & 1) ? AT_PS1F : AT_PS0F));
        const float* gsr = smf + AT_GS + jtp * 32 + jq * 4;
        float z0 = fv + gsr[0]; z0 = z0 >= 0.f ? z0 : 0.2f * z0;
        float z1 = fv + gsr[1]; z1 = z1 >= 0.f ? z1 : 0.2f * z1;
        float z2 = fv + gsr[2]; z2 = z2 >= 0.f ? z2 : 0.2f * z2;
        float z3 = fv + gsr[3]; z3 = z3 >= 0.f ? z3 : 0.2f * z3;
        float p0 = (v.x > 0) ? __expf(z0 - Mi) : 0.f;
        float p1 = (v.y > 0) ? __expf(z1 - Mi) : 0.f;
        float p2 = (v.z > 0) ? __expf(z2 - Mi) : 0.f;
        float p3 = (v.w > 0) ? __expf(z3 - Mi) : 0.f;
        __half2 h01 = __float22half2_rn(make_float2(p0, p1));
        __half2 h23 = __float22half2_rn(make_float2(p2, p3));
        float2 r01 = __half22float2(h01);
        float2 r23 = __half22float2(h23);
        dloc += (r01.x + r01.y) + (r23.x + r23.y);   // denominator matches fp16 weights
        *(uint2*)(ps + irow * 40 + jq * 4) =
            make_uint2(*(uint32_t*)&h01, *(uint32_t*)&h23);
    };
    auto do_mma = [&](int jt) {
        const __half* psh = (const __half*)(smf + ((jt & 1) ? AT_PS1F : AT_PS0F));
        const __half* hsh = (const __half*)(smf + ((jt & 1) ? AT_HS1F : AT_HS0F));
        #pragma unroll
        for (int ks = 0; ks < 2; ks++) {
            uint32_t afr[2][4];
            #pragma unroll
            for (int ma = 0; ma < 2; ma++) {
                const __half* pb = psh + (wiq * 32 + ma * 16 + g) * 40 + ks * 16 + tig * 2;
                afr[ma][0] = *(const uint32_t*)(pb);
                afr[ma][1] = *(const uint32_t*)(pb + 8 * 40);
                afr[ma][2] = *(const uint32_t*)(pb + 8);
                afr[ma][3] = *(const uint32_t*)(pb + 8 * 40 + 8);
            }
            uint32_t bfr[4][2];
            #pragma unroll
            for (int na = 0; na < 4; na++) {
                const __half* hbp = hsh + (wo * 32 + na * 8 + g) * 40 + ks * 16 + tig * 2;
                bfr[na][0] = *(const uint32_t*)(hbp);
                bfr[na][1] = *(const uint32_t*)(hbp + 8);
            }
            #pragma unroll
            for (int ma = 0; ma < 2; ma++)
                #pragma unroll
                for (int na = 0; na < 4; na++)
                    mma_f16(acc[ma][na], afr[ma], bfr[na]);
        }
    };

    store_p(0, A0);
    ld_adj_at(2, A0, adjrow);
    CP_WAIT0();
    __syncthreads();

    for (int jt = 0; jt < 64; jt += 2) {
        {
            if (jt < 63) cp_h(jt + 1);
            do_mma(jt);
            if (jt < 63) store_p(jt + 1, A1);
            if (jt + 3 < 64) ld_adj_at(jt + 3, A1, adjrow);
            if (jt < 63) CP_WAIT0();
            __syncthreads();
        }
        {
            int jo = jt + 1;
            if (jo < 63) cp_h(jo + 1);
            do_mma(jo);
            if (jo < 63) store_p(jo + 1, A0);
            if (jo + 3 < 64) ld_adj_at(jo + 3, A0, adjrow);
            if (jo < 63) CP_WAIT0();
            __syncthreads();
        }
    }

    smf[AT_DSUM + jq * 128 + irow] = dloc;
    __syncthreads();

    #pragma unroll
    for (int ma = 0; ma < 2; ma++) {
        int ra = wiq * 32 + ma * 16 + g;
        int rb = ra + 8;
        float da = 0.f, db = 0.f;
        #pragma unroll
        for (int s = 0; s < 8; s++) {
            da += smf[AT_DSUM + s * 128 + ra];
            db += smf[AT_DSUM + s * 128 + rb];
        }
        float inva = (da > 0.f) ? 1.f / da : 0.f;
        float invb = (db > 0.f) ? 1.f / db : 0.f;
        float* outa = out + ((size_t)b * NN + i0 + ra) * FOUT;
        float* outb = out + ((size_t)b * NN + i0 + rb) * FOUT;
        #pragma unroll
        for (int na = 0; na < 4; na++) {
            int col = wo * 32 + na * 8 + tig * 2;
            float v0 = acc[ma][na][0] * inva;
            float v1 = acc[ma][na][1] * inva;
            float v2 = acc[ma][na][2] * invb;
            float v3 = acc[ma][na][3] * invb;
            v0 = v0 > 0.f ? v0 : expm1f(v0);
            v1 = v1 > 0.f ? v1 : expm1f(v1);
            v2 = v2 > 0.f ? v2 : expm1f(v2);
            v3 = v3 > 0.f ? v3 : expm1f(v3);
            *(float2*)(outa + col) = make_float2(v0, v1);
            *(float2*)(outb + col) = make_float2(v2, v3);
        }
    }
}

// ---------------------------------------------------------------------------
extern "C" void kernel_launch(void* const* d_in, const int* in_sizes, int n_in,
                              void* d_out, int out_size)
{
    const float* x   = (const float*)d_in[0];
    const int*   adj = (const int*)d_in[1];
    const float* W   = (const float*)d_in[2];
    const float* a   = (const float*)d_in[3];
    float*       out = (float*)d_out;

    cudaFuncSetAttribute(gemm_h_kernel, cudaFuncAttributeMaxDynamicSharedMemorySize, GH_SMEM);
    cudaFuncSetAttribute(attn_kernel,   cudaFuncAttributeMaxDynamicSharedMemorySize, ATTN_SMEM);

    wv_kernel<<<64, 256>>>(W, a);
    gemm_h_kernel<<<128, 512, GH_SMEM>>>(x, W);
    fg_kernel<<<2048, 256>>>(x);
    attn_kernel<<<128, 1024, ATTN_SMEM>>>(adj, out);
}

// round 17
// speedup vs baseline: 1.4024x; 1.0657x over previous
#include <cuda_runtime.h>
#include <cuda_fp16.h>
#include <math.h>
#include <stdint.h>

#define BB   8
#define NN   2048
#define FIN  512
#define FOUT 256

__device__ __half g_hT[(size_t)BB * FOUT * NN];  // h transposed, fp16: [b][o][n]
__device__ float  g_f[BB * NN];
__device__ float  g_g[BB * NN];
__device__ float  g_w12[2 * FIN];

__device__ __forceinline__ uint32_t to_tf32(float f) {
    uint32_t r; asm("cvt.rna.tf32.f32 %0, %1;" : "=r"(r) : "f"(f)); return r;
}
__device__ __forceinline__ void mma_tf32(float* d, const uint32_t* a, const uint32_t* b) {
    asm volatile(
        "mma.sync.aligned.m16n8k8.row.col.f32.tf32.tf32.f32 "
        "{%0,%1,%2,%3}, {%4,%5,%6,%7}, {%8,%9}, {%0,%1,%2,%3};"
        : "+f"(d[0]), "+f"(d[1]), "+f"(d[2]), "+f"(d[3])
        : "r"(a[0]), "r"(a[1]), "r"(a[2]), "r"(a[3]), "r"(b[0]), "r"(b[1]));
}
__device__ __forceinline__ void mma_f16(float* d, const uint32_t* a, const uint32_t* b) {
    asm volatile(
        "mma.sync.aligned.m16n8k16.row.col.f32.f16.f16.f32 "
        "{%0,%1,%2,%3}, {%4,%5,%6,%7}, {%8,%9}, {%0,%1,%2,%3};"
        : "+f"(d[0]), "+f"(d[1]), "+f"(d[2]), "+f"(d[3])
        : "r"(a[0]), "r"(a[1]), "r"(a[2]), "r"(a[3]), "r"(b[0]), "r"(b[1]));
}
__device__ __forceinline__ void ldsm_x4(uint32_t& r0, uint32_t& r1, uint32_t& r2,
                                        uint32_t& r3, uint32_t addr) {
    asm volatile("ldmatrix.sync.aligned.m8n8.x4.shared.b16 {%0,%1,%2,%3}, [%4];"
                 : "=r"(r0), "=r"(r1), "=r"(r2), "=r"(r3) : "r"(addr));
}
__device__ __forceinline__ uint32_t smem_u32(const void* p) {
    uint32_t a;
    asm("{ .reg .u64 t; cvta.to.shared.u64 t, %1; cvt.u32.u64 %0, t; }" : "=r"(a) : "l"(p));
    return a;
}
__device__ __forceinline__ void cp16(uint32_t dst, const void* src) {
    asm volatile("cp.async.cg.shared.global [%0], [%1], 16;" :: "r"(dst), "l"(src));
}
#define CP_COMMIT() asm volatile("cp.async.commit_group;" ::: "memory")
#define CP_WAIT0()  asm volatile("cp.async.wait_group 0;" ::: "memory")

// ===========================================================================
// Kernel 0: w1 = W @ a1, w2 = W @ a2 (fp32).
// ===========================================================================
__global__ __launch_bounds__(256, 1)
void wv_kernel(const float* __restrict__ W, const float* __restrict__ a)
{
    const int warp = threadIdx.x >> 5, lane = threadIdx.x & 31;
    const int k = blockIdx.x * 8 + warp;
    const float* wr = W + (size_t)k * FOUT;
    float s1 = 0.f, s2 = 0.f;
    #pragma unroll
    for (int q = 0; q < 2; q++) {
        float4 wv = *(const float4*)(wr + lane * 8 + q * 4);
        float4 a1 = *(const float4*)(a + lane * 8 + q * 4);
        float4 a2 = *(const float4*)(a + FOUT + lane * 8 + q * 4);
        s1 += wv.x * a1.x + wv.y * a1.y + wv.z * a1.z + wv.w * a1.w;
        s2 += wv.x * a2.x + wv.y * a2.y + wv.z * a2.z + wv.w * a2.w;
    }
    #pragma unroll
    for (int d = 16; d >= 1; d >>= 1) {
        s1 += __shfl_xor_sync(0xffffffffu, s1, d);
        s2 += __shfl_xor_sync(0xffffffffu, s2, d);
    }
    if (lane == 0) { g_w12[k] = s1; g_w12[FIN + k] = s2; }
}

// ===========================================================================
// Kernel 2: f = x @ w1, g = x @ w2 (fp32 FFMA).
// ===========================================================================
__global__ __launch_bounds__(256, 1)
void fg_kernel(const float* __restrict__ x)
{
    const int warp = threadIdx.x >> 5, lane = threadIdx.x & 31;
    const int row = blockIdx.x * 8 + warp;
    const float* xr = x + (size_t)row * FIN;
    float f = 0.f, g = 0.f;
    #pragma unroll
    for (int q = 0; q < 4; q++) {
        float4 v  = *(const float4*)(xr + lane * 4 + q * 128);
        float4 w1 = *(const float4*)(g_w12 + lane * 4 + q * 128);
        float4 w2 = *(const float4*)(g_w12 + FIN + lane * 4 + q * 128);
        f += v.x * w1.x + v.y * w1.y + v.z * w1.z + v.w * w1.w;
        g += v.x * w2.x + v.y * w2.y + v.z * w2.z + v.w * w2.w;
    }
    #pragma unroll
    for (int d = 16; d >= 1; d >>= 1) {
        f += __shfl_xor_sync(0xffffffffu, f, d);
        g += __shfl_xor_sync(0xffffffffu, g, d);
    }
    if (lane == 0) { g_f[row] = f; g_g[row] = g; }
}

// ===========================================================================
// Kernel 1: h = x @ W (single tf32 MMA), epilogue -> g_hT fp16. (R16, proven)
// ===========================================================================
#define XS_OFF 0
#define XS_SZ  2560
#define WS_OFF 5120
#define WS_SZ  4224
#define GH_SMEM 69632
#define HSTP 136

__global__ __launch_bounds__(512, 1)
void gemm_h_kernel(const float* __restrict__ x, const float* __restrict__ W)
{
    extern __shared__ float sm[];
    const uint32_t sb = smem_u32(sm);

    const int t    = threadIdx.x;
    const int m0   = blockIdx.x * 128;
    const int warp = t >> 5, lane = t & 31;
    const int g    = lane >> 2, tig = lane & 3;
    const int wi   = warp >> 2, wo = warp & 3;

    const int xrow = t >> 2, xseg = (t & 3) * 4;
    const int wrow = t >> 5, wseg = (t & 31) * 8;
    const float* xsrc = x + (size_t)(m0 + xrow) * FIN + xseg;
    const float* wsrc = W + (size_t)wrow * FOUT + wseg;

    auto issue = [&](int s) {
        uint32_t xd = sb + (XS_OFF + (s & 1) * XS_SZ + xrow * 20 + xseg) * 4;
        cp16(xd, xsrc + s * 16);
        uint32_t wd = sb + (WS_OFF + (s & 1) * WS_SZ + wrow * 264 + wseg) * 4;
        cp16(wd,      wsrc + (size_t)s * 16 * FOUT);
        cp16(wd + 16, wsrc + (size_t)s * 16 * FOUT + 4);
        CP_COMMIT();
    };

    float acc[2][8][4];
    #pragma unroll
    for (int ma = 0; ma < 2; ma++)
        #pragma unroll
        for (int na = 0; na < 8; na++)
            #pragma unroll
            for (int c = 0; c < 4; c++) acc[ma][na][c] = 0.f;

    issue(0);
    CP_WAIT0();
    __syncthreads();

    for (int s = 0; s < 32; s++) {
        if (s < 31) issue(s + 1);
        const float* xs = sm + XS_OFF + (s & 1) * XS_SZ;
        const float* ws = sm + WS_OFF + (s & 1) * WS_SZ;

        #pragma unroll
        for (int ks = 0; ks < 2; ks++) {
            uint32_t bhi[8][2];
            #pragma unroll
            for (int na = 0; na < 8; na++) {
                int o = wo * 64 + na * 8 + g;
                bhi[na][0] = to_tf32(ws[(ks * 8 + tig) * 264 + o]);
                bhi[na][1] = to_tf32(ws[(ks * 8 + tig + 4) * 264 + o]);
            }
            #pragma unroll
            for (int ma = 0; ma < 2; ma++) {
                int R = wi * 32 + ma * 16;
                uint32_t ahi[4];
                ahi[0] = to_tf32(xs[(R + g) * 20 + ks * 8 + tig]);
                ahi[1] = to_tf32(xs[(R + g + 8) * 20 + ks * 8 + tig]);
                ahi[2] = to_tf32(xs[(R + g) * 20 + ks * 8 + tig + 4]);
                ahi[3] = to_tf32(xs[(R + g + 8) * 20 + ks * 8 + tig + 4]);
                #pragma unroll
                for (int na = 0; na < 8; na++)
                    mma_tf32(acc[ma][na], ahi, bhi[na]);
            }
        }
        if (s < 31) CP_WAIT0();
        __syncthreads();
    }

    __half* hst = (__half*)sm;
    #pragma unroll
    for (int ma = 0; ma < 2; ma++) {
        int ra = wi * 32 + ma * 16 + g;
        int rb = ra + 8;
        #pragma unroll
        for (int na = 0; na < 8; na++) {
            int col = wo * 64 + na * 8 + tig * 2;
            hst[(col    ) * HSTP + ra] = __float2half_rn(acc[ma][na][0]);
            hst[(col + 1) * HSTP + ra] = __float2half_rn(acc[ma][na][1]);
            hst[(col    ) * HSTP + rb] = __float2half_rn(acc[ma][na][2]);
            hst[(col + 1) * HSTP + rb] = __float2half_rn(acc[ma][na][3]);
        }
    }
    __syncthreads();

    {
        const int bidx = m0 >> 11;
        const int n0   = m0 & 2047;
        const int o    = t >> 1;
        const int seg  = (t & 1) * 64;
        __half* dst = g_hT + ((size_t)(bidx * 256 + o)) * NN + n0 + seg;
        const __half* srcr = hst + o * HSTP + seg;
        #pragma unroll
        for (int q = 0; q < 8; q++)
            *(uint4*)(dst + q * 8) = *(const uint4*)(srcr + q * 8);
    }
}

// ===========================================================================
// Kernel 3: attention, fp16 m16n8k16 MMA + softmax shift (R16) with
// consumer fragment loads via ldmatrix.x4 (8 LDSM vs 32 LDS per warp/jt).
// ===========================================================================
#define AT_DSUM 0
#define AT_GS   1024
#define AT_RED  3072
#define AT_PS0F 3104
#define AT_PS1F 5664
#define AT_HS0F 8224
#define AT_HS1F 13344
#define ATTN_SMEM (18464 * 4)

__global__ __launch_bounds__(1024, 1)
void attn_kernel(const int* __restrict__ adj, float* __restrict__ out)
{
    extern __shared__ float smf[];
    const uint32_t sb = smem_u32(smf);

    const int t    = threadIdx.x;
    const int b    = blockIdx.x >> 4;
    const int i0   = (blockIdx.x & 15) << 7;
    const int warp = t >> 5, lane = t & 31;
    const int g    = lane >> 2, tig = lane & 3;
    const int wiq  = warp >> 3, wo = warp & 7;

    const int irow = t >> 3;
    const int jq   = t & 7;
    const int ho   = t >> 2;
    const int hseg = (t & 3) * 8;

    // ldmatrix lane address components (in halves)
    const int a_row  = (lane & 7) + ((lane >> 3) & 1) * 8;   // row within 16
    const int a_col8 = ((lane >> 4) & 1) * 8;                // k chunk
    const int b_row  = (lane >> 4) * 8 + (lane & 7);         // o within 16 (pair-local)
    const int b_col8 = ((lane >> 3) & 1) * 8;

    float acc[2][4][4];
    #pragma unroll
    for (int ma = 0; ma < 2; ma++)
        #pragma unroll
        for (int na = 0; na < 4; na++)
            #pragma unroll
            for (int c = 0; c < 4; c++) acc[ma][na][c] = 0.f;
    float dloc = 0.f;

    auto cp_h = [&](int jt) {
        const __half* src = g_hT + ((size_t)(b * 256 + ho)) * NN + jt * 32 + hseg;
        uint32_t dst = sb + ((jt & 1) ? AT_HS1F : AT_HS0F) * 4 + ho * 80 + hseg * 2;
        cp16(dst, src);
        CP_COMMIT();
    };

    // ---- prologue ----
    cp_h(0);
    const int* adjrow = adj + ((size_t)b * NN + i0 + irow) * NN + jq * 4;
    int4 A0, A1;
    A0 = *(const int4*)(adjrow);
    A1 = *(const int4*)(adjrow + 32);
    float gm = -1e30f;
    for (int j = t; j < NN; j += 1024) {
        float v = g_g[b * NN + j];
        smf[AT_GS + j] = v;
        gm = fmaxf(gm, v);
    }
    const float fv = g_f[b * NN + i0 + irow];
    #pragma unroll
    for (int d = 16; d >= 1; d >>= 1) gm = fmaxf(gm, __shfl_xor_sync(0xffffffffu, gm, d));
    if (lane == 0) smf[AT_RED + warp] = gm;
    __syncthreads();
    if (warp == 0) {
        float v = smf[AT_RED + lane];
        #pragma unroll
        for (int d = 16; d >= 1; d >>= 1) v = fmaxf(v, __shfl_xor_sync(0xffffffffu, v, d));
        if (lane == 0) smf[AT_RED] = v;
    }
    __syncthreads();
    const float gmaxv = smf[AT_RED];
    float Mi = fv + gmaxv;
    Mi = (Mi >= 0.f) ? Mi : 0.2f * Mi;

    auto store_p = [&](int jtp, const int4& v) {
        __half* ps = (__half*)(smf + ((jtp & 1) ? AT_PS1F : AT_PS0F));
        const float* gsr = smf + AT_GS + jtp * 32 + jq * 4;
        float z0 = fv + gsr[0]; z0 = z0 >= 0.f ? z0 : 0.2f * z0;
        float z1 = fv + gsr[1]; z1 = z1 >= 0.f ? z1 : 0.2f * z1;
        float z2 = fv + gsr[2]; z2 = z2 >= 0.f ? z2 : 0.2f * z2;
        float z3 = fv + gsr[3]; z3 = z3 >= 0.f ? z3 : 0.2f * z3;
        float p0 = (v.x > 0) ? __expf(z0 - Mi) : 0.f;
        float p1 = (v.y > 0) ? __expf(z1 - Mi) : 0.f;
        float p2 = (v.z > 0) ? __expf(z2 - Mi) : 0.f;
        float p3 = (v.w > 0) ? __expf(z3 - Mi) : 0.f;
        __half2 h01 = __float22half2_rn(make_float2(p0, p1));
        __half2 h23 = __float22half2_rn(make_float2(p2, p3));
        float2 r01 = __half22float2(h01);
        float2 r23 = __half22float2(h23);
        dloc += (r01.x + r01.y) + (r23.x + r23.y);
        *(uint2*)(ps + irow * 40 + jq * 4) =
            make_uint2(*(uint32_t*)&h01, *(uint32_t*)&h23);
    };
    auto do_mma = [&](int jt) {
        const uint32_t psb = sb + ((jt & 1) ? AT_PS1F : AT_PS0F) * 4;
        const uint32_t hsb = sb + ((jt & 1) ? AT_HS1F : AT_HS0F) * 4;
        #pragma unroll
        for (int ks = 0; ks < 2; ks++) {
            uint32_t afr[2][4];
            #pragma unroll
            for (int ma = 0; ma < 2; ma++) {
                uint32_t addr = psb + ((wiq * 32 + ma * 16 + a_row) * 40
                                       + ks * 16 + a_col8) * 2;
                ldsm_x4(afr[ma][0], afr[ma][1], afr[ma][2], afr[ma][3], addr);
            }
            uint32_t bfr[4][2];
            #pragma unroll
            for (int pr = 0; pr < 2; pr++) {
                uint32_t addr = hsb + ((wo * 32 + pr * 16 + b_row) * 40
                                       + ks * 16 + b_col8) * 2;
                ldsm_x4(bfr[pr*2][0], bfr[pr*2][1], bfr[pr*2+1][0], bfr[pr*2+1][1], addr);
            }
            #pragma unroll
            for (int ma = 0; ma < 2; ma++)
                #pragma unroll
                for (int na = 0; na < 4; na++)
                    mma_f16(acc[ma][na], afr[ma], bfr[na]);
        }
    };

    store_p(0, A0);
    A0 = *(const int4*)(adjrow + 2 * 32);
    CP_WAIT0();
    __syncthreads();

    for (int jt = 0; jt < 64; jt += 2) {
        {
            if (jt < 63) cp_h(jt + 1);
            do_mma(jt);
            if (jt < 63) store_p(jt + 1, A1);
            if (jt + 3 < 64) A1 = *(const int4*)(adjrow + (jt + 3) * 32);
            if (jt < 63) CP_WAIT0();
            __syncthreads();
        }
        {
            int jo = jt + 1;
            if (jo < 63) cp_h(jo + 1);
            do_mma(jo);
            if (jo < 63) store_p(jo + 1, A0);
            if (jo + 3 < 64) A0 = *(const int4*)(adjrow + (jo + 3) * 32);
            if (jo < 63) CP_WAIT0();
            __syncthreads();
        }
    }

    smf[AT_DSUM + jq * 128 + irow] = dloc;
    __syncthreads();

    #pragma unroll
    for (int ma = 0; ma < 2; ma++) {
        int ra = wiq * 32 + ma * 16 + g;
        int rb = ra + 8;
        float da = 0.f, db = 0.f;
        #pragma unroll
        for (int s = 0; s < 8; s++) {
            da += smf[AT_DSUM + s * 128 + ra];
            db += smf[AT_DSUM + s * 128 + rb];
        }
        float inva = (da > 0.f) ? 1.f / da : 0.f;
        float invb = (db > 0.f) ? 1.f / db : 0.f;
        float* outa = out + ((size_t)b * NN + i0 + ra) * FOUT;
        float* outb = out + ((size_t)b * NN + i0 + rb) * FOUT;
        #pragma unroll
        for (int na = 0; na < 4; na++) {
            int col = wo * 32 + na * 8 + tig * 2;
            float v0 = acc[ma][na][0] * inva;
            float v1 = acc[ma][na][1] * inva;
            float v2 = acc[ma][na][2] * invb;
            float v3 = acc[ma][na][3] * invb;
            v0 = v0 > 0.f ? v0 : expm1f(v0);
            v1 = v1 > 0.f ? v1 : expm1f(v1);
            v2 = v2 > 0.f ? v2 : expm1f(v2);
            v3 = v3 > 0.f ? v3 : expm1f(v3);
            *(float2*)(outa + col) = make_float2(v0, v1);
            *(float2*)(outb + col) = make_float2(v2, v3);
        }
    }
}

// ---------------------------------------------------------------------------
extern "C" void kernel_launch(void* const* d_in, const int* in_sizes, int n_in,
                              void* d_out, int out_size)
{
    const float* x   = (const float*)d_in[0];
    const int*   adj = (const int*)d_in[1];
    const float* W   = (const float*)d_in[2];
    const float* a   = (const float*)d_in[3];
    float*       out = (float*)d_out;

    cudaFuncSetAttribute(gemm_h_kernel, cudaFuncAttributeMaxDynamicSharedMemorySize, GH_SMEM);
    cudaFuncSetAttribute(attn_kernel,   cudaFuncAttributeMaxDynamicSharedMemorySize, ATTN_SMEM);

    wv_kernel<<<64, 256>>>(W, a);
    gemm_h_kernel<<<128, 512, GH_SMEM>>>(x, W);
    fg_kernel<<<2048, 256>>>(x);
    attn_kernel<<<128, 1024, ATTN_SMEM>>>(adj, out);
}